// round 16
// baseline (speedup 1.0000x reference)
#include <cuda_runtime.h>
#include <cuda_fp16.h>
#include <cstdint>

// ----------------------------------------------------------------------------
// BaseGR hetero-SAGE on GB300 — R16.
// vs R15: layer-1 persistent GEMM moved to occupancy 2 (64-row A items again,
// SMEM 104.4KB, launch_bounds(256,2), 296 CTAs) — same bubble-hiding lever
// that gained 45us on the pred GEMM in R15. Numerics unchanged.
// ----------------------------------------------------------------------------

#define NG 5000
#define NU 100000
#define NI 20000
#define H 128
#define HH (H*H)
#define E_UG 300000
#define E_UI 600000
#define E_GI 200000

// ---------------- fp32: combined biases ----------------
__device__ float g_f[4 * H];

// ---------------- fp16 tables -------------------------------------------------
#define OH_HU  0
#define OH_HI  (OH_HU  + NU*H)
#define OH_HU1 (OH_HI  + NI*H)
#define OH_HI1 (OH_HU1 + NU*H)
#define OH_AIU (OH_HI1 + NI*H)
#define OH_AUI (OH_AIU + NU*H)
#define OH_AUG (OH_AUI + NI*H)
#define OH_AIG (OH_AUG + NG*H)
#define OH_HG1 (OH_AIG + NG*H)
#define OH_BUG (OH_HG1 + NG*H)
#define OH_BIG (OH_BUG + NG*H)
#define OH_REP (OH_BIG + NG*H)
#define OH_PW  (OH_REP + NG*H)
#define OH_W   (OH_PW  + NI*H)
#define H_TOTAL (OH_W + 9*HH)
__device__ __half g_h[H_TOTAL];

// weight slots (fp16, HH each)
#define SL_W1L3 0
#define SL_WC0  1
#define SL_W1L2 2
#define SL_WC1  3
#define SL_W1L0 4
#define SL_W1L5 5
#define SL_W2L0 6
#define SL_WC2  7
#define SL_W2L5 8

// ---------------- int scratch ----------------
#define OI_CNT_G1 0
#define OI_CNT_G2 (OI_CNT_G1 + NG)
#define OI_CNT_U  (OI_CNT_G2 + NG)
#define OI_CNT_I  (OI_CNT_U  + NU)
#define CNT_TOTAL (OI_CNT_I  + NI)
#define OI_RP_G1  CNT_TOTAL
#define OI_RP_G2  (OI_RP_G1 + NG + 1)
#define OI_RP_U   (OI_RP_G2 + NG + 1)
#define OI_RP_I   (OI_RP_U  + NU + 1)
#define OI_CUR_G1 (OI_RP_I  + NI + 1)
#define OI_CUR_G2 (OI_CUR_G1 + NG)
#define OI_CUR_U  (OI_CUR_G2 + NG)
#define OI_CUR_I  (OI_CUR_U  + NU)
#define OI_COL_G1 (OI_CUR_I  + NI)
#define OI_COL_G2 (OI_COL_G1 + E_UG)
#define OI_COL_U  (OI_COL_G2 + E_GI)
#define OI_COL_I  (OI_COL_U  + E_UI)
#define I_TOTAL   (OI_COL_I  + E_UI)
__device__ int g_i[I_TOTAL];

// ======================= helpers =============================================
__device__ __forceinline__ uint32_t smem_u32(const void* p) {
    uint32_t a;
    asm("{ .reg .u64 t; cvta.to.shared.u64 t, %1; cvt.u32.u64 %0, t; }"
        : "=r"(a) : "l"(p));
    return a;
}

#define LDSM4(r, addr) \
    asm volatile("ldmatrix.sync.aligned.m8n8.x4.shared.b16 {%0,%1,%2,%3}, [%4];" \
                 : "=r"((r)[0]), "=r"((r)[1]), "=r"((r)[2]), "=r"((r)[3]) \
                 : "r"(addr))

#define MMA_F16(c, a, b0, b1) \
    asm volatile("mma.sync.aligned.m16n8k16.row.col.f32.f16.f16.f32 " \
                 "{%0,%1,%2,%3}, {%4,%5,%6,%7}, {%8,%9}, {%0,%1,%2,%3};" \
                 : "+f"((c)[0]), "+f"((c)[1]), "+f"((c)[2]), "+f"((c)[3]) \
                 : "r"((a)[0]), "r"((a)[1]), "r"((a)[2]), "r"((a)[3]), \
                   "r"(b0), "r"(b1))

#define CPA16(dst, src, sz) \
    asm volatile("cp.async.cg.shared.global [%0], [%1], 16, %2;" \
                 :: "r"(dst), "l"(src), "r"(sz))
#define CP_COMMIT() asm volatile("cp.async.commit_group;" ::: "memory")
#define CP_WAIT0()  asm volatile("cp.async.wait_group 0;" ::: "memory")
#define CP_WAIT1()  asm volatile("cp.async.wait_group 1;" ::: "memory")

// ======================= front: gather (fp16) + degree counts ================
__global__ void k_front(const float* __restrict__ emb_u, const int* __restrict__ x_u,
                        const float* __restrict__ emb_i, const int* __restrict__ x_i,
                        const int* __restrict__ ug_dst, const int* __restrict__ gi_src,
                        const int* __restrict__ ui_src, const int* __restrict__ ui_dst,
                        __half* __restrict__ hh, int* __restrict__ ib)
{
    const int t0 = blockIdx.x * blockDim.x + threadIdx.x;
    if (t0 < (NU + NI) * 32) {
        const float* emb; const int* x; __half* outh; int u;
        if (t0 < NU * 32) { emb = emb_u; x = x_u; outh = hh + OH_HU; u = t0; }
        else { emb = emb_i; x = x_i; outh = hh + OH_HI; u = t0 - NU * 32; }
        int r = u >> 5, c = u & 31;
        float4 v = ((const float4*)emb)[(size_t)x[r] * 32 + c];
        __half2 p0 = __floats2half2_rn(v.x, v.y);
        __half2 p1 = __floats2half2_rn(v.z, v.w);
        uint2 hv;
        hv.x = *(uint32_t*)&p0;
        hv.y = *(uint32_t*)&p1;
        ((uint2*)outh)[(size_t)r * 32 + c] = hv;
    }
    if (t0 < E_UG) atomicAdd(&ib[OI_CNT_G1 + ug_dst[t0]], 1);
    else if (t0 < E_UG + E_GI) atomicAdd(&ib[OI_CNT_G2 + gi_src[t0 - E_UG]], 1);
    else if (t0 < E_UG + E_GI + E_UI) atomicAdd(&ib[OI_CNT_U + ui_src[t0 - E_UG - E_GI]], 1);
    else if (t0 < E_UG + E_GI + 2*E_UI) atomicAdd(&ib[OI_CNT_I + ui_dst[t0 - E_UG - E_GI - E_UI]], 1);
}

// ======================= CSR scan + bucket ===================================
__global__ void k_scan4(int* __restrict__ ib)
{
    const int* cnt; int* rp; int* cur; int n;
    switch (blockIdx.x) {
        case 0: cnt = ib + OI_CNT_G1; rp = ib + OI_RP_G1; cur = ib + OI_CUR_G1; n = NG; break;
        case 1: cnt = ib + OI_CNT_G2; rp = ib + OI_RP_G2; cur = ib + OI_CUR_G2; n = NG; break;
        case 2: cnt = ib + OI_CNT_U;  rp = ib + OI_RP_U;  cur = ib + OI_CUR_U;  n = NU; break;
        default: cnt = ib + OI_CNT_I; rp = ib + OI_RP_I;  cur = ib + OI_CUR_I;  n = NI; break;
    }
    __shared__ int ssum[1024];
    const int t = threadIdx.x;
    const int chunk = (n + 1023) / 1024;
    int beg = t * chunk;
    int end = beg + chunk; if (end > n) end = n;
    if (beg > n) beg = n;
    int s = 0;
    for (int i = beg; i < end; i++) s += cnt[i];
    ssum[t] = s;
    __syncthreads();
    for (int off = 1; off < 1024; off <<= 1) {
        int v = (t >= off) ? ssum[t - off] : 0;
        __syncthreads();
        ssum[t] += v;
        __syncthreads();
    }
    int prefix = (t == 0) ? 0 : ssum[t - 1];
    for (int i = beg; i < end; i++) {
        rp[i]  = prefix;
        cur[i] = prefix;
        prefix += cnt[i];
    }
    if (t == 1023) rp[n] = ssum[1023];
}

__global__ void k_bucket_all(const int* __restrict__ ug_src, const int* __restrict__ ug_dst,
                             const int* __restrict__ ui_src, const int* __restrict__ ui_dst,
                             const int* __restrict__ gi_src, const int* __restrict__ gi_dst,
                             int* __restrict__ ib)
{
    int t = blockIdx.x * blockDim.x + threadIdx.x;
    if (t < E_UG) {
        int p = atomicAdd(&ib[OI_CUR_G1 + ug_dst[t]], 1);
        ib[OI_COL_G1 + p] = ug_src[t];
    } else if (t < E_UG + E_GI) {
        int e = t - E_UG;
        int p = atomicAdd(&ib[OI_CUR_G2 + gi_src[e]], 1);
        ib[OI_COL_G2 + p] = gi_dst[e];
    } else if (t < E_UG + E_GI + E_UI) {
        int e = t - E_UG - E_GI;
        int p = atomicAdd(&ib[OI_CUR_U + ui_src[e]], 1);
        ib[OI_COL_U + p] = ui_dst[e];
    } else if (t < E_UG + E_GI + 2*E_UI) {
        int e = t - E_UG - E_GI - E_UI;
        int p = atomicAdd(&ib[OI_CUR_I + ui_dst[e]], 1);
        ib[OI_COL_I + p] = ui_src[e];
    }
}

// ======================= segment mean (fp16 in -> fp16 out) ==================
__device__ __forceinline__ void agg_row(const int* __restrict__ rp, const int* __restrict__ col,
                                        const __half* __restrict__ feat,
                                        __half* __restrict__ outp, int row, int lane)
{
    int beg = rp[row], end = rp[row + 1];
    float4 acc = make_float4(0.f, 0.f, 0.f, 0.f);
    const uint2* fv = (const uint2*)feat;
    int e = beg;
    for (; e + 8 <= end; e += 8) {
        int s[8];
#pragma unroll
        for (int q = 0; q < 8; q++) s[q] = __ldg(&col[e + q]);
        uint2 v[8];
#pragma unroll
        for (int q = 0; q < 8; q++) v[q] = __ldg(&fv[(size_t)s[q] * 32 + lane]);
#pragma unroll
        for (int q = 0; q < 8; q++) {
            float2 f0 = __half22float2(*(__half2*)&v[q].x);
            float2 f1 = __half22float2(*(__half2*)&v[q].y);
            acc.x += f0.x; acc.y += f0.y; acc.z += f1.x; acc.w += f1.y;
        }
    }
    for (; e < end; e++) {
        int sx = __ldg(&col[e]);
        uint2 v = __ldg(&fv[(size_t)sx * 32 + lane]);
        float2 f0 = __half22float2(*(__half2*)&v.x);
        float2 f1 = __half22float2(*(__half2*)&v.y);
        acc.x += f0.x; acc.y += f0.y; acc.z += f1.x; acc.w += f1.y;
    }
    float inv = (end > beg) ? 1.f / (float)(end - beg) : 0.f;
    __half2 p0 = __floats2half2_rn(acc.x * inv, acc.y * inv);
    __half2 p1 = __floats2half2_rn(acc.z * inv, acc.w * inv);
    uint2 o;
    o.x = *(uint32_t*)&p0;
    o.y = *(uint32_t*)&p1;
    ((uint2*)outp)[(size_t)row * 32 + lane] = o;
}

__global__ void k_agg_all(const int* __restrict__ ib, __half* __restrict__ hh)
{
    int w = (int)((blockIdx.x * blockDim.x + threadIdx.x) >> 5);
    int lane = threadIdx.x & 31;
    if (w < NU)
        agg_row(ib + OI_RP_U, ib + OI_COL_U, hh + OH_HI, hh + OH_AIU, w, lane);
    else if (w < NU + NI)
        agg_row(ib + OI_RP_I, ib + OI_COL_I, hh + OH_HU, hh + OH_AUI, w - NU, lane);
    else if (w < NU + NI + NG)
        agg_row(ib + OI_RP_G1, ib + OI_COL_G1, hh + OH_HU, hh + OH_AUG, w - NU - NI, lane);
    else if (w < NU + NI + 2*NG)
        agg_row(ib + OI_RP_G2, ib + OI_COL_G2, hh + OH_HI, hh + OH_AIG, w - NU - NI - NG, lane);
}

__global__ void k_agg_all2(const int* __restrict__ ib, __half* __restrict__ hh)
{
    int w = (int)((blockIdx.x * blockDim.x + threadIdx.x) >> 5);
    int lane = threadIdx.x & 31;
    if (w < NG)
        agg_row(ib + OI_RP_G1, ib + OI_COL_G1, hh + OH_HU1, hh + OH_BUG, w, lane);
    else if (w < 2*NG)
        agg_row(ib + OI_RP_G2, ib + OI_COL_G2, hh + OH_HI1, hh + OH_BIG, w - NG, lane);
}

// ======================= weight prep: combine + transpose -> fp16 + biases ===
__global__ void __launch_bounds__(256)
k_halfW(const float* __restrict__ W1l, const float* __restrict__ W1r,
        const float* __restrict__ W2l, const float* __restrict__ W2r,
        const float* __restrict__ b1, const float* __restrict__ b2,
        __half* __restrict__ dst9)
{
    const float* srcA; const float* srcB = nullptr;
    switch (blockIdx.z) {
        case 0: srcA = W1l + 3*HH; break;
        case 1: srcA = W1r + 1*HH; srcB = W1r + 3*HH; break;
        case 2: srcA = W1l + 2*HH; break;
        case 3: srcA = W1r + 2*HH; srcB = W1r + 4*HH; break;
        case 4: srcA = W1l + 0*HH; break;
        case 5: srcA = W1l + 5*HH; break;
        case 6: srcA = W2l + 0*HH; break;
        case 7: srcA = W2r + 0*HH; srcB = W2r + 5*HH; break;
        default: srcA = W2l + 5*HH; break;
    }
    __half* dst = dst9 + (size_t)blockIdx.z * HH;
    __shared__ float t[32][33];
    int nblk = blockIdx.x * 32;
    int kblk = blockIdx.y * 32;
    int tx = threadIdx.x, ty = threadIdx.y;
#pragma unroll
    for (int i = ty; i < 32; i += 8) {
        size_t gi = (size_t)(kblk + i) * H + nblk + tx;
        float v = srcA[gi];
        if (srcB) v += srcB[gi];
        t[i][tx] = v;
    }
    __syncthreads();
#pragma unroll
    for (int i = ty; i < 32; i += 8)
        dst[(size_t)(nblk + i) * H + kblk + tx] = __float2half(t[tx][i]);
    if (blockIdx.z == 0 && blockIdx.x == 0 && blockIdx.y == 0 && ty == 0) {
#pragma unroll
        for (int q = 0; q < 4; q++) {
            int i = q * 32 + tx;
            g_f[0*H + i] = b1[1*H + i] + b1[3*H + i];
            g_f[1*H + i] = b1[2*H + i] + b1[4*H + i];
            g_f[2*H + i] = b1[0*H + i] + b1[5*H + i];
            g_f[3*H + i] = b2[0*H + i] + b2[5*H + i];
        }
    }
}

// pred_W [H, NI] fp32 -> [NI, H] fp16 (transposed)
__global__ void __launch_bounds__(256)
k_halfB(const float* __restrict__ W, __half* __restrict__ out)
{
    __shared__ float t[32][33];
    int nblk = blockIdx.x * 32;
    int kblk = blockIdx.y * 32;
    int tx = threadIdx.x, ty = threadIdx.y;
#pragma unroll
    for (int i = ty; i < 32; i += 8)
        t[i][tx] = W[(size_t)(kblk + i) * NI + nblk + tx];
    __syncthreads();
#pragma unroll
    for (int i = ty; i < 32; i += 8)
        out[(size_t)(nblk + i) * H + kblk + tx] = __float2half(t[tx][i]);
}

// ======================= common GEMM constants ===============================
#define PK   136
#define ROWB (PK * 2)          // 272 B per row
#define TILEB (128 * ROWB)     // 34816 B
#define HTILE (64 * ROWB)      // 17408 B

// ======================= layer-2 GEMM (3 fp16 terms, occ 2) ==================
struct GemmArgs {
    const __half* A[3];
    const __half* W[3];
    const float* bias;
    __half* Ch;
    int M, nterms;
};

#define SMEM_GH (2 * TILEB)    // 69632

__global__ void __launch_bounds__(256, 2)
k_gemm_h(GemmArgs g)
{
    extern __shared__ char sm[];
    const int tid  = threadIdx.x;
    const int wid  = tid >> 5;
    const int lane = tid & 31;
    const int wm   = wid >> 1;
    const int wn   = wid & 1;
    const int m0   = blockIdx.x * 128;

    const uint32_t sbase  = smem_u32(sm);
    const uint32_t a_loff = (uint32_t)(lane & 15) * ROWB + (uint32_t)(lane >> 4) * 16;
    const uint32_t b_loff = (uint32_t)(((lane >> 4) * 8) + (lane & 7)) * ROWB
                          + (uint32_t)((lane >> 3) & 1) * 16;

    float c[2][8][4];
#pragma unroll
    for (int i = 0; i < 2; i++)
#pragma unroll
        for (int j = 0; j < 8; j++)
#pragma unroll
            for (int q = 0; q < 4; q++) c[i][j][q] = 0.f;

#pragma unroll 1
    for (int t = 0; t < g.nterms; t++) {
        const uint4* wsrc = (const uint4*)g.W[t];
        const uint4* asrc = (const uint4*)g.A[t];
#pragma unroll 4
        for (int i = tid; i < 2048; i += 256) {
            int row = i >> 4, cq = i & 15;
            uint32_t so = (uint32_t)row * ROWB + cq * 16;
            *(uint4*)(sm + so) = __ldg(&wsrc[row * 16 + cq]);
            uint4 va = make_uint4(0, 0, 0, 0);
            if (m0 + row < g.M) va = __ldg(&asrc[(size_t)(m0 + row) * 16 + cq]);
            *(uint4*)(sm + TILEB + so) = va;
        }
        __syncthreads();
        uint32_t aB = sbase + TILEB + (uint32_t)wm * 32 * ROWB + a_loff;
        uint32_t bB = sbase + (uint32_t)wn * 64 * ROWB + b_loff;
#pragma unroll
        for (int ks = 0; ks < 8; ks++) {
            uint32_t a[2][4], b[4][4];
            LDSM4(a[0], aB + ks * 32);
            LDSM4(a[1], aB + ks * 32 + 16 * ROWB);
#pragma unroll
            for (int q = 0; q < 4; q++)
                LDSM4(b[q], bB + ks * 32 + q * 16 * ROWB);
#pragma unroll
            for (int ma = 0; ma < 2; ma++)
#pragma unroll
                for (int na = 0; na < 8; na++)
                    MMA_F16(c[ma][na], a[ma],
                            b[na >> 1][(na & 1) * 2], b[na >> 1][(na & 1) * 2 + 1]);
        }
        __syncthreads();
    }

    const int gid = lane >> 2;
    const int tq  = (lane & 3) * 2;
#pragma unroll
    for (int ma = 0; ma < 2; ma++) {
#pragma unroll
        for (int na = 0; na < 8; na++) {
            int mrow = m0 + wm * 32 + ma * 16 + gid;
            int ncol = wn * 64 + na * 8 + tq;
            float2 bv = *(const float2*)(g.bias + ncol);
#pragma unroll
            for (int hrow = 0; hrow < 2; hrow++) {
                int mr = mrow + hrow * 8;
                if (mr >= g.M) continue;
                float v0 = fmaxf(c[ma][na][hrow*2 + 0] + bv.x, 0.f);
                float v1 = fmaxf(c[ma][na][hrow*2 + 1] + bv.y, 0.f);
                __half2 hv = __floats2half2_rn(v0, v1);
                *(__half2*)(g.Ch + (size_t)mr * H + ncol) = hv;
            }
        }
    }
}

// ======================= persistent layer-1 GEMM (fp16, occ 2, 64-row items) =
struct LJob {
    const __half* Ah0; const __half* Ah1;
    const __half* W0;  const __half* W1;
    const float* bias;
    __half* Ch;
    int M, ntiles, ctaBase, nctas;
};
struct LJob3 { LJob j[3]; };

#define SMEM_GL (2 * TILEB + 2 * HTILE)   // 104448 (x2 per SM)
#define NCTA_L 296

__device__ __forceinline__ void loadA64(uint32_t dst, const uint4* ap,
                                        int m0_, int M, int tid)
{
#pragma unroll 2
    for (int i = tid; i < 1024; i += 256) {
        int row = i >> 4, cq = i & 15;
        int gr = m0_ + row;
        int sz = (gr < M) ? 16 : 0;
        if (gr >= M) gr = M - 1;
        CPA16(dst + (uint32_t)row * ROWB + cq * 16, ap + (size_t)gr * 16 + cq, sz);
    }
}

__global__ void __launch_bounds__(256, 2)
k_gemm_l(LJob3 js)
{
    extern __shared__ char sm[];
    const int tid  = threadIdx.x;
    const int wid  = tid >> 5;
    const int lane = tid & 31;
    const int wm   = wid >> 2;            // 0..1 (32 rows each)
    const int wn   = wid & 3;             // 0..3 (32 cols each)

    int ji = (blockIdx.x >= (uint32_t)js.j[2].ctaBase) ? 2
           : (blockIdx.x >= (uint32_t)js.j[1].ctaBase) ? 1 : 0;
    const LJob g = js.j[ji];
    const int idx = blockIdx.x - g.ctaBase;
    const int beg = (int)((long long)idx * g.ntiles / g.nctas);
    const int end = (int)((long long)(idx + 1) * g.ntiles / g.nctas);
    if (beg >= end) return;

    const uint32_t sbase = smem_u32(sm);
    const uint32_t sA    = sbase + 2 * TILEB;

    // resident W load: 2 fp16 tiles
    {
        const uint4* w0 = (const uint4*)g.W0;
        const uint4* w1 = (const uint4*)g.W1;
#pragma unroll 4
        for (int i = tid; i < 4096; i += 256) {
            int tl = i >> 11;
            int row = (i >> 4) & 127;
            int cq = i & 15;
            const uint4* src = tl ? w1 : w0;
            CPA16(sbase + (uint32_t)tl * TILEB + (uint32_t)row * ROWB + cq * 16,
                  src + (size_t)row * 16 + cq, 16);
        }
    }
    loadA64(sA, (const uint4*)g.Ah0, beg * 64, g.M, tid);
    CP_COMMIT();

    const uint32_t a_loff = (uint32_t)(lane & 15) * ROWB + (uint32_t)(lane >> 4) * 16;
    const uint32_t b_loff = (uint32_t)(((lane >> 4) * 8) + (lane & 7)) * ROWB
                          + (uint32_t)((lane >> 3) & 1) * 16;
    const int gid = lane >> 2;
    const int tq  = (lane & 3) * 2;

    float c[2][4][4];
    const int nit = (end - beg) * 2;
    int buf = 0;

#pragma unroll 1
    for (int it = 0; it < nit; it++) {
        const int tile = beg + (it >> 1);
        const int term = it & 1;
        if (it + 1 < nit) {
            int ntile = beg + ((it + 1) >> 1);
            int nterm = (it + 1) & 1;
            const uint4* ap = (const uint4*)(nterm ? g.Ah1 : g.Ah0);
            loadA64(sA + (uint32_t)(buf ^ 1) * HTILE, ap, ntile * 64, g.M, tid);
            CP_COMMIT();
            CP_WAIT1();
        } else {
            CP_WAIT0();
        }
        __syncthreads();

        if (term == 0) {
#pragma unroll
            for (int i = 0; i < 2; i++)
#pragma unroll
                for (int j = 0; j < 4; j++)
#pragma unroll
                    for (int q = 0; q < 4; q++) c[i][j][q] = 0.f;
        }

        uint32_t aB = sA + (uint32_t)buf * HTILE + (uint32_t)wm * 32 * ROWB + a_loff;
        uint32_t bB = sbase + (uint32_t)term * TILEB + (uint32_t)wn * 32 * ROWB + b_loff;
#pragma unroll
        for (int ks = 0; ks < 8; ks++) {
            uint32_t a[2][4], b[2][4];
            LDSM4(a[0], aB + ks * 32);
            LDSM4(a[1], aB + ks * 32 + 16 * ROWB);
            LDSM4(b[0], bB + ks * 32);
            LDSM4(b[1], bB + ks * 32 + 16 * ROWB);
#pragma unroll
            for (int ma = 0; ma < 2; ma++)
#pragma unroll
                for (int na = 0; na < 4; na++)
                    MMA_F16(c[ma][na], a[ma],
                            b[na >> 1][(na & 1) * 2], b[na >> 1][(na & 1) * 2 + 1]);
        }

        if (term == 1) {
            int m0_ = tile * 64;
#pragma unroll
            for (int ma = 0; ma < 2; ma++) {
#pragma unroll
                for (int na = 0; na < 4; na++) {
                    int mrow = m0_ + wm * 32 + ma * 16 + gid;
                    int ncol = wn * 32 + na * 8 + tq;
                    float2 bv = *(const float2*)(g.bias + ncol);
#pragma unroll
                    for (int hrow = 0; hrow < 2; hrow++) {
                        int mr = mrow + hrow * 8;
                        if (mr >= g.M) continue;
                        float v0 = fmaxf(c[ma][na][hrow*2 + 0] + bv.x, 0.f);
                        float v1 = fmaxf(c[ma][na][hrow*2 + 1] + bv.y, 0.f);
                        __half2 hv = __floats2half2_rn(v0, v1);
                        *(__half2*)(g.Ch + (size_t)mr * H + ncol) = hv;
                    }
                }
            }
        }
        __syncthreads();
        buf ^= 1;
    }
}

// ======================= persistent pred GEMM (fp32 acc, occupancy 2) ========
#define NTN ((NI + 127) / 128)    // 157
#define NTM ((NG + 127) / 128)    // 40
#define NT_TOT (NTN * NTM)        // 6280
#define NCTA_PRED 296             // 2 CTAs per SM
#define SMEM_PREDH (3 * TILEB)    // 104448

__device__ __forceinline__ void pred_load1(uint32_t dst, const uint4* gp,
                                           int r0_, int rmax, int tid)
{
#pragma unroll 4
    for (int i = tid; i < 2048; i += 256) {
        int row = i >> 4, cq = i & 15;
        int gr = r0_ + row;
        int sz = (gr < rmax) ? 16 : 0;
        if (gr >= rmax) gr = rmax - 1;
        CPA16(dst + (uint32_t)row * ROWB + cq * 16, gp + (size_t)gr * 16 + cq, sz);
    }
}

__global__ void __launch_bounds__(256, 2)
k_mma_pred(const __half* __restrict__ A, const __half* __restrict__ B,
           const float* __restrict__ bias, float* __restrict__ out)
{
    extern __shared__ char sm[];
    const int tid  = threadIdx.x;
    const int wid  = tid >> 5;
    const int lane = tid & 31;
    const int wm   = wid >> 1;
    const int wn   = wid & 1;

    const uint32_t sbase = smem_u32(sm);
    const uint32_t sB    = sbase + TILEB;

    const uint4* gA = (const uint4*)A;
    const uint4* gB = (const uint4*)B;

    const int beg = (int)((long long)blockIdx.x * NT_TOT / NCTA_PRED);
    const int end = (int)((long long)(blockIdx.x + 1) * NT_TOT / NCTA_PRED);

    const uint32_t a_loff = (uint32_t)(lane & 15) * ROWB + (uint32_t)(lane >> 4) * 16;
    const uint32_t b_loff = (uint32_t)(((lane >> 4) * 8) + (lane & 7)) * ROWB
                          + (uint32_t)((lane >> 3) & 1) * 16;
    const int gid = lane >> 2;
    const int tq  = (lane & 3) * 2;

    int cur_m = -1;
    int buf = 0;

#pragma unroll 1
    for (int t = beg; t < end; ++t) {
        int tm = t / NTN, tn = t - tm * NTN;
        if (tm != cur_m) {
            CP_WAIT0();
            __syncthreads();
            pred_load1(sbase, gA, tm * 128, NG, tid);
            pred_load1(sB, gB, tn * 128, NI, tid);
            CP_COMMIT();
            cur_m = tm;
            buf = 0;
            if (t + 1 < end && (t + 1) / NTN == cur_m) {
                pred_load1(sB + TILEB, gB, (tn + 1) * 128, NI, tid);
                CP_COMMIT();
                CP_WAIT1();
            } else {
                CP_WAIT0();
            }
            __syncthreads();
        } else {
            if (t + 1 < end && (t + 1) / NTN == cur_m) {
                pred_load1(sB + (uint32_t)(buf ^ 1) * TILEB, gB, (tn + 1) * 128, NI, tid);
                CP_COMMIT();
                CP_WAIT1();
            } else {
                CP_WAIT0();
            }
            __syncthreads();
        }

        float c[2][8][4];
#pragma unroll
        for (int i = 0; i < 2; i++)
#pragma unroll
            for (int j = 0; j < 8; j++)
#pragma unroll
                for (int q = 0; q < 4; q++) c[i][j][q] = 0.f;

        uint32_t aB = sbase + (uint32_t)wm * 32 * ROWB + a_loff;
        uint32_t bB = sB + (uint32_t)buf * TILEB + (uint32_t)wn * 64 * ROWB + b_loff;
#pragma unroll
        for (int ks = 0; ks < 8; ks++) {
            uint32_t a[2][4], b[4][4];
            LDSM4(a[0], aB + ks * 32);
            LDSM4(a[1], aB + ks * 32 + 16 * ROWB);
#pragma unroll
            for (int q = 0; q < 4; q++)
                LDSM4(b[q], bB + ks * 32 + q * 16 * ROWB);
#pragma unroll
            for (int ma = 0; ma < 2; ma++)
#pragma unroll
                for (int na = 0; na < 8; na++)
                    MMA_F16(c[ma][na], a[ma],
                            b[na >> 1][(na & 1) * 2], b[na >> 1][(na & 1) * 2 + 1]);
        }

        int m0_ = tm * 128, n0_ = tn * 128;
#pragma unroll
        for (int ma = 0; ma < 2; ma++) {
#pragma unroll
            for (int na = 0; na < 8; na++) {
                int mrow = m0_ + wm * 32 + ma * 16 + gid;
                int ncol = n0_ + wn * 64 + na * 8 + tq;
                if (ncol >= NI) continue;
                float2 bv = *(const float2*)(bias + ncol);
                if (mrow < NG) {
                    float2 v = make_float2(c[ma][na][0] + bv.x, c[ma][na][1] + bv.y);
                    *(float2*)(out + (size_t)mrow * NI + ncol) = v;
                }
                if (mrow + 8 < NG) {
                    float2 v = make_float2(c[ma][na][2] + bv.x, c[ma][na][3] + bv.y);
                    *(float2*)(out + (size_t)(mrow + 8) * NI + ncol) = v;
                }
            }
        }
        __syncthreads();
        buf ^= 1;
    }
}

// ---------------------------------------------------------------------------
extern "C" void kernel_launch(void* const* d_in, const int* in_sizes, int n_in,
                              void* d_out, int out_size)
{
    const int*   x_user   = (const int*)  d_in[1];
    const int*   x_item   = (const int*)  d_in[2];
    const float* emb_user = (const float*)d_in[4];
    const float* emb_item = (const float*)d_in[5];
    const float* W1l      = (const float*)d_in[6];
    const float* W1r      = (const float*)d_in[7];
    const float* b1       = (const float*)d_in[8];
    const float* W2l      = (const float*)d_in[9];
    const float* W2r      = (const float*)d_in[10];
    const float* b2       = (const float*)d_in[11];
    const float* pred_W   = (const float*)d_in[12];
    const float* pred_b   = (const float*)d_in[13];
    const int*   ug_src   = (const int*)  d_in[14];
    const int*   ug_dst   = (const int*)  d_in[15];
    const int*   ui_src   = (const int*)  d_in[16];
    const int*   ui_dst   = (const int*)  d_in[17];
    const int*   gi_src   = (const int*)  d_in[18];
    const int*   gi_dst   = (const int*)  d_in[19];
    float* out = (float*)d_out;

    float* fb = nullptr; int* ib = nullptr; __half* hh = nullptr;
    cudaGetSymbolAddress((void**)&fb, g_f);
    cudaGetSymbolAddress((void**)&ib, g_i);
    cudaGetSymbolAddress((void**)&hh, g_h);

    cudaFuncSetAttribute(k_gemm_h, cudaFuncAttributeMaxDynamicSharedMemorySize, SMEM_GH);
    cudaFuncSetAttribute(k_gemm_l, cudaFuncAttributeMaxDynamicSharedMemorySize, SMEM_GL);
    cudaFuncSetAttribute(k_mma_pred, cudaFuncAttributeMaxDynamicSharedMemorySize, SMEM_PREDH);

    // (1) zero degree counts
    cudaMemsetAsync(ib + OI_CNT_G1, 0, (size_t)CNT_TOTAL * sizeof(int));

    // (2) gather fp16 + degree counts (merged)
    {
        int tot = (NU + NI) * 32;
        k_front<<<(tot + 255) / 256, 256>>>(emb_user, x_user, emb_item, x_item,
                                            ug_dst, gi_src, ui_src, ui_dst, hh, ib);
    }

    // (3) CSR row pointers, (4) bucket
    k_scan4<<<4, 1024>>>(ib);
    {
        int tot = E_UG + E_GI + 2 * E_UI;
        k_bucket_all<<<(tot + 255) / 256, 256>>>(ug_src, ug_dst, ui_src, ui_dst,
                                                 gi_src, gi_dst, ib);
    }

    // (5) layer-1 aggregations  <-- ncu capture slot
    {
        int warps = NU + NI + 2 * NG;
        k_agg_all<<<(warps + 7) / 8, 256>>>(ib, hh);
    }

    // (6,7) weight prep
    k_halfW<<<dim3(4, 4, 9), dim3(32, 8)>>>(W1l, W1r, W2l, W2r, b1, b2, hh + OH_W);
    k_halfB<<<dim3(NI / 32, H / 32), dim3(32, 8)>>>(pred_W, hh + OH_PW);

    // (8) layer-1 GEMMs: one persistent launch at occupancy 2 (64-row items)
    {
        LJob3 js;
        js.j[0].Ah0 = hh + OH_AIU; js.j[0].Ah1 = hh + OH_HU;
        js.j[0].W0 = hh + OH_W + SL_W1L3*HH; js.j[0].W1 = hh + OH_W + SL_WC0*HH;
        js.j[0].bias = fb + 0*H; js.j[0].Ch = hh + OH_HU1;
        js.j[0].M = NU; js.j[0].ntiles = (NU + 63) / 64;       // 1563
        js.j[0].ctaBase = 0;   js.j[0].nctas = 236;
        js.j[1].Ah0 = hh + OH_AUI; js.j[1].Ah1 = hh + OH_HI;
        js.j[1].W0 = hh + OH_W + SL_W1L2*HH; js.j[1].W1 = hh + OH_W + SL_WC1*HH;
        js.j[1].bias = fb + 1*H; js.j[1].Ch = hh + OH_HI1;
        js.j[1].M = NI; js.j[1].ntiles = (NI + 63) / 64;       // 313
        js.j[1].ctaBase = 236; js.j[1].nctas = 48;
        js.j[2].Ah0 = hh + OH_AUG; js.j[2].Ah1 = hh + OH_AIG;
        js.j[2].W0 = hh + OH_W + SL_W1L0*HH; js.j[2].W1 = hh + OH_W + SL_W1L5*HH;
        js.j[2].bias = fb + 2*H; js.j[2].Ch = hh + OH_HG1;
        js.j[2].M = NG; js.j[2].ntiles = (NG + 63) / 64;       // 79
        js.j[2].ctaBase = 284; js.j[2].nctas = 12;
        k_gemm_l<<<NCTA_L, 256, SMEM_GL>>>(js);
    }

    // (9) layer-2 aggregations
    k_agg_all2<<<(2 * NG + 7) / 8, 256>>>(ib, hh);

    // (10) layer-2 group GEMM (3 fp16 terms) -> REP fp16
    {
        GemmArgs a;
        a.A[0] = hh + OH_BUG; a.W[0] = hh + OH_W + SL_W2L0*HH;
        a.A[1] = hh + OH_HG1; a.W[1] = hh + OH_W + SL_WC2*HH;
        a.A[2] = hh + OH_BIG; a.W[2] = hh + OH_W + SL_W2L5*HH;
        a.bias = fb + 3*H;
        a.Ch = hh + OH_REP;
        a.M = NG; a.nterms = 3;
        k_gemm_h<<<(NG + 127) / 128, 256, SMEM_GH>>>(a);
    }

    // (11) persistent fp32-acc prediction GEMM at occupancy 2
    k_mma_pred<<<NCTA_PRED, 256, SMEM_PREDH>>>(hh + OH_REP, hh + OH_PW, pred_b, out);
    (void)in_sizes; (void)n_in; (void)out_size;
}

// round 17
// speedup vs baseline: 1.0420x; 1.0420x over previous
#include <cuda_runtime.h>
#include <cuda_fp16.h>
#include <cstdint>

// ----------------------------------------------------------------------------
// BaseGR hetero-SAGE on GB300 — R17.
// vs R16 (numerically identical): (1) weight prep (halfW/halfB) folded into
// k_front's grid as extra block ranges — runs concurrently with gather/count
// instead of serializing mid-chain; (2) 32-bit byte addressing in agg_row
// (tables < 4GB) to cut ALU issue on the issue-bound aggregation kernel.
// ----------------------------------------------------------------------------

#define NG 5000
#define NU 100000
#define NI 20000
#define H 128
#define HH (H*H)
#define E_UG 300000
#define E_UI 600000
#define E_GI 200000

// ---------------- fp32: combined biases ----------------
__device__ float g_f[4 * H];

// ---------------- fp16 tables -------------------------------------------------
#define OH_HU  0
#define OH_HI  (OH_HU  + NU*H)
#define OH_HU1 (OH_HI  + NI*H)
#define OH_HI1 (OH_HU1 + NU*H)
#define OH_AIU (OH_HI1 + NI*H)
#define OH_AUI (OH_AIU + NU*H)
#define OH_AUG (OH_AUI + NI*H)
#define OH_AIG (OH_AUG + NG*H)
#define OH_HG1 (OH_AIG + NG*H)
#define OH_BUG (OH_HG1 + NG*H)
#define OH_BIG (OH_BUG + NG*H)
#define OH_REP (OH_BIG + NG*H)
#define OH_PW  (OH_REP + NG*H)
#define OH_W   (OH_PW  + NI*H)
#define H_TOTAL (OH_W + 9*HH)
__device__ __half g_h[H_TOTAL];

// weight slots (fp16, HH each)
#define SL_W1L3 0
#define SL_WC0  1
#define SL_W1L2 2
#define SL_WC1  3
#define SL_W1L0 4
#define SL_W1L5 5
#define SL_W2L0 6
#define SL_WC2  7
#define SL_W2L5 8

// ---------------- int scratch ----------------
#define OI_CNT_G1 0
#define OI_CNT_G2 (OI_CNT_G1 + NG)
#define OI_CNT_U  (OI_CNT_G2 + NG)
#define OI_CNT_I  (OI_CNT_U  + NU)
#define CNT_TOTAL (OI_CNT_I  + NI)
#define OI_RP_G1  CNT_TOTAL
#define OI_RP_G2  (OI_RP_G1 + NG + 1)
#define OI_RP_U   (OI_RP_G2 + NG + 1)
#define OI_RP_I   (OI_RP_U  + NU + 1)
#define OI_CUR_G1 (OI_RP_I  + NI + 1)
#define OI_CUR_G2 (OI_CUR_G1 + NG)
#define OI_CUR_U  (OI_CUR_G2 + NG)
#define OI_CUR_I  (OI_CUR_U  + NU)
#define OI_COL_G1 (OI_CUR_I  + NI)
#define OI_COL_G2 (OI_COL_G1 + E_UG)
#define OI_COL_U  (OI_COL_G2 + E_GI)
#define OI_COL_I  (OI_COL_U  + E_UI)
#define I_TOTAL   (OI_COL_I  + E_UI)
__device__ int g_i[I_TOTAL];

// ======================= helpers =============================================
__device__ __forceinline__ uint32_t smem_u32(const void* p) {
    uint32_t a;
    asm("{ .reg .u64 t; cvta.to.shared.u64 t, %1; cvt.u32.u64 %0, t; }"
        : "=r"(a) : "l"(p));
    return a;
}

#define LDSM4(r, addr) \
    asm volatile("ldmatrix.sync.aligned.m8n8.x4.shared.b16 {%0,%1,%2,%3}, [%4];" \
                 : "=r"((r)[0]), "=r"((r)[1]), "=r"((r)[2]), "=r"((r)[3]) \
                 : "r"(addr))

#define MMA_F16(c, a, b0, b1) \
    asm volatile("mma.sync.aligned.m16n8k16.row.col.f32.f16.f16.f32 " \
                 "{%0,%1,%2,%3}, {%4,%5,%6,%7}, {%8,%9}, {%0,%1,%2,%3};" \
                 : "+f"((c)[0]), "+f"((c)[1]), "+f"((c)[2]), "+f"((c)[3]) \
                 : "r"((a)[0]), "r"((a)[1]), "r"((a)[2]), "r"((a)[3]), \
                   "r"(b0), "r"(b1))

#define CPA16(dst, src, sz) \
    asm volatile("cp.async.cg.shared.global [%0], [%1], 16, %2;" \
                 :: "r"(dst), "l"(src), "r"(sz))
#define CP_COMMIT() asm volatile("cp.async.commit_group;" ::: "memory")
#define CP_WAIT0()  asm volatile("cp.async.wait_group 0;" ::: "memory")
#define CP_WAIT1()  asm volatile("cp.async.wait_group 1;" ::: "memory")

// ======================= front: gather + counts + weight prep (fused) ========
#define NB_GATHER (((NU + NI) * 32 + 255) / 256)   // 15000
#define NB_HALFB  ((NI / 32) * (H / 32))           // 2500
#define NB_HALFW  (4 * 4 * 9)                      // 144
#define NB_FRONT  (NB_GATHER + NB_HALFB + NB_HALFW)

__global__ void __launch_bounds__(256)
k_front(const float* __restrict__ emb_u, const int* __restrict__ x_u,
        const float* __restrict__ emb_i, const int* __restrict__ x_i,
        const int* __restrict__ ug_dst, const int* __restrict__ gi_src,
        const int* __restrict__ ui_src, const int* __restrict__ ui_dst,
        const float* __restrict__ W1l, const float* __restrict__ W1r,
        const float* __restrict__ W2l, const float* __restrict__ W2r,
        const float* __restrict__ b1, const float* __restrict__ b2,
        const float* __restrict__ pred_W,
        __half* __restrict__ hh, int* __restrict__ ib)
{
    const int bid = blockIdx.x;
    if (bid < NB_GATHER) {
        // ---- gather fp16 + degree counts ----
        const int t0 = bid * 256 + threadIdx.x;
        if (t0 < (NU + NI) * 32) {
            const float* emb; const int* x; __half* outh; int u;
            if (t0 < NU * 32) { emb = emb_u; x = x_u; outh = hh + OH_HU; u = t0; }
            else { emb = emb_i; x = x_i; outh = hh + OH_HI; u = t0 - NU * 32; }
            int r = u >> 5, c = u & 31;
            float4 v = ((const float4*)emb)[(size_t)x[r] * 32 + c];
            __half2 p0 = __floats2half2_rn(v.x, v.y);
            __half2 p1 = __floats2half2_rn(v.z, v.w);
            uint2 hv;
            hv.x = *(uint32_t*)&p0;
            hv.y = *(uint32_t*)&p1;
            ((uint2*)outh)[(size_t)r * 32 + c] = hv;
        }
        if (t0 < E_UG) atomicAdd(&ib[OI_CNT_G1 + ug_dst[t0]], 1);
        else if (t0 < E_UG + E_GI) atomicAdd(&ib[OI_CNT_G2 + gi_src[t0 - E_UG]], 1);
        else if (t0 < E_UG + E_GI + E_UI) atomicAdd(&ib[OI_CNT_U + ui_src[t0 - E_UG - E_GI]], 1);
        else if (t0 < E_UG + E_GI + 2*E_UI) atomicAdd(&ib[OI_CNT_I + ui_dst[t0 - E_UG - E_GI - E_UI]], 1);
        return;
    }

    __shared__ float t[32][33];
    const int tx = threadIdx.x & 31;
    const int ty = threadIdx.x >> 5;    // 0..7

    if (bid < NB_GATHER + NB_HALFB) {
        // ---- pred_W [H, NI] -> [NI, H] fp16 transposed ----
        int b2i = bid - NB_GATHER;
        int nblk = (b2i % (NI / 32)) * 32;
        int kblk = (b2i / (NI / 32)) * 32;
#pragma unroll
        for (int i = ty; i < 32; i += 8)
            t[i][tx] = pred_W[(size_t)(kblk + i) * NI + nblk + tx];
        __syncthreads();
        __half* out = hh + OH_PW;
#pragma unroll
        for (int i = ty; i < 32; i += 8)
            out[(size_t)(nblk + i) * H + kblk + tx] = __float2half(t[tx][i]);
        return;
    }

    // ---- layer weights: combine + transpose -> fp16 (+ biases on block 0) ----
    {
        int b3 = bid - NB_GATHER - NB_HALFB;    // 0..143
        int z = b3 / 16;
        int rem = b3 % 16;
        int nblk = (rem % 4) * 32;
        int kblk = (rem / 4) * 32;
        const float* srcA; const float* srcB = nullptr;
        switch (z) {
            case 0: srcA = W1l + 3*HH; break;
            case 1: srcA = W1r + 1*HH; srcB = W1r + 3*HH; break;
            case 2: srcA = W1l + 2*HH; break;
            case 3: srcA = W1r + 2*HH; srcB = W1r + 4*HH; break;
            case 4: srcA = W1l + 0*HH; break;
            case 5: srcA = W1l + 5*HH; break;
            case 6: srcA = W2l + 0*HH; break;
            case 7: srcA = W2r + 0*HH; srcB = W2r + 5*HH; break;
            default: srcA = W2l + 5*HH; break;
        }
        __half* dst = hh + OH_W + (size_t)z * HH;
#pragma unroll
        for (int i = ty; i < 32; i += 8) {
            size_t gi = (size_t)(kblk + i) * H + nblk + tx;
            float v = srcA[gi];
            if (srcB) v += srcB[gi];
            t[i][tx] = v;
        }
        __syncthreads();
#pragma unroll
        for (int i = ty; i < 32; i += 8)
            dst[(size_t)(nblk + i) * H + kblk + tx] = __float2half(t[tx][i]);
        if (b3 == 0 && ty == 0) {
#pragma unroll
            for (int q = 0; q < 4; q++) {
                int i = q * 32 + tx;
                g_f[0*H + i] = b1[1*H + i] + b1[3*H + i];
                g_f[1*H + i] = b1[2*H + i] + b1[4*H + i];
                g_f[2*H + i] = b1[0*H + i] + b1[5*H + i];
                g_f[3*H + i] = b2[0*H + i] + b2[5*H + i];
            }
        }
    }
}

// ======================= CSR scan + bucket ===================================
__global__ void k_scan4(int* __restrict__ ib)
{
    const int* cnt; int* rp; int* cur; int n;
    switch (blockIdx.x) {
        case 0: cnt = ib + OI_CNT_G1; rp = ib + OI_RP_G1; cur = ib + OI_CUR_G1; n = NG; break;
        case 1: cnt = ib + OI_CNT_G2; rp = ib + OI_RP_G2; cur = ib + OI_CUR_G2; n = NG; break;
        case 2: cnt = ib + OI_CNT_U;  rp = ib + OI_RP_U;  cur = ib + OI_CUR_U;  n = NU; break;
        default: cnt = ib + OI_CNT_I; rp = ib + OI_RP_I;  cur = ib + OI_CUR_I;  n = NI; break;
    }
    __shared__ int ssum[1024];
    const int t = threadIdx.x;
    const int chunk = (n + 1023) / 1024;
    int beg = t * chunk;
    int end = beg + chunk; if (end > n) end = n;
    if (beg > n) beg = n;
    int s = 0;
    for (int i = beg; i < end; i++) s += cnt[i];
    ssum[t] = s;
    __syncthreads();
    for (int off = 1; off < 1024; off <<= 1) {
        int v = (t >= off) ? ssum[t - off] : 0;
        __syncthreads();
        ssum[t] += v;
        __syncthreads();
    }
    int prefix = (t == 0) ? 0 : ssum[t - 1];
    for (int i = beg; i < end; i++) {
        rp[i]  = prefix;
        cur[i] = prefix;
        prefix += cnt[i];
    }
    if (t == 1023) rp[n] = ssum[1023];
}

__global__ void k_bucket_all(const int* __restrict__ ug_src, const int* __restrict__ ug_dst,
                             const int* __restrict__ ui_src, const int* __restrict__ ui_dst,
                             const int* __restrict__ gi_src, const int* __restrict__ gi_dst,
                             int* __restrict__ ib)
{
    int t = blockIdx.x * blockDim.x + threadIdx.x;
    if (t < E_UG) {
        int p = atomicAdd(&ib[OI_CUR_G1 + ug_dst[t]], 1);
        ib[OI_COL_G1 + p] = ug_src[t];
    } else if (t < E_UG + E_GI) {
        int e = t - E_UG;
        int p = atomicAdd(&ib[OI_CUR_G2 + gi_src[e]], 1);
        ib[OI_COL_G2 + p] = gi_dst[e];
    } else if (t < E_UG + E_GI + E_UI) {
        int e = t - E_UG - E_GI;
        int p = atomicAdd(&ib[OI_CUR_U + ui_src[e]], 1);
        ib[OI_COL_U + p] = ui_dst[e];
    } else if (t < E_UG + E_GI + 2*E_UI) {
        int e = t - E_UG - E_GI - E_UI;
        int p = atomicAdd(&ib[OI_CUR_I + ui_dst[e]], 1);
        ib[OI_COL_I + p] = ui_src[e];
    }
}

// ======================= segment mean (fp16, 32-bit addressing) ==============
__device__ __forceinline__ void agg_row(const int* __restrict__ rp, const int* __restrict__ col,
                                        const __half* __restrict__ feat,
                                        __half* __restrict__ outp, int row, int lane)
{
    int beg = rp[row], end = rp[row + 1];
    float4 acc = make_float4(0.f, 0.f, 0.f, 0.f);
    const char* f8 = (const char*)feat;
    const uint32_t loff = (uint32_t)lane * 8u;
    int e = beg;
    for (; e + 8 <= end; e += 8) {
        uint32_t o[8];
#pragma unroll
        for (int q = 0; q < 8; q++)
            o[q] = (uint32_t)__ldg(&col[e + q]) * 256u + loff;
        uint2 v[8];
#pragma unroll
        for (int q = 0; q < 8; q++) v[q] = __ldg((const uint2*)(f8 + o[q]));
#pragma unroll
        for (int q = 0; q < 8; q++) {
            float2 f0 = __half22float2(*(__half2*)&v[q].x);
            float2 f1 = __half22float2(*(__half2*)&v[q].y);
            acc.x += f0.x; acc.y += f0.y; acc.z += f1.x; acc.w += f1.y;
        }
    }
    for (; e < end; e++) {
        uint32_t o = (uint32_t)__ldg(&col[e]) * 256u + loff;
        uint2 v = __ldg((const uint2*)(f8 + o));
        float2 f0 = __half22float2(*(__half2*)&v.x);
        float2 f1 = __half22float2(*(__half2*)&v.y);
        acc.x += f0.x; acc.y += f0.y; acc.z += f1.x; acc.w += f1.y;
    }
    float inv = (end > beg) ? 1.f / (float)(end - beg) : 0.f;
    __half2 p0 = __floats2half2_rn(acc.x * inv, acc.y * inv);
    __half2 p1 = __floats2half2_rn(acc.z * inv, acc.w * inv);
    uint2 o;
    o.x = *(uint32_t*)&p0;
    o.y = *(uint32_t*)&p1;
    *(uint2*)((char*)outp + (uint32_t)row * 256u + loff) = o;
}

__global__ void k_agg_all(const int* __restrict__ ib, __half* __restrict__ hh)
{
    int w = (int)((blockIdx.x * blockDim.x + threadIdx.x) >> 5);
    int lane = threadIdx.x & 31;
    if (w < NU)
        agg_row(ib + OI_RP_U, ib + OI_COL_U, hh + OH_HI, hh + OH_AIU, w, lane);
    else if (w < NU + NI)
        agg_row(ib + OI_RP_I, ib + OI_COL_I, hh + OH_HU, hh + OH_AUI, w - NU, lane);
    else if (w < NU + NI + NG)
        agg_row(ib + OI_RP_G1, ib + OI_COL_G1, hh + OH_HU, hh + OH_AUG, w - NU - NI, lane);
    else if (w < NU + NI + 2*NG)
        agg_row(ib + OI_RP_G2, ib + OI_COL_G2, hh + OH_HI, hh + OH_AIG, w - NU - NI - NG, lane);
}

__global__ void k_agg_all2(const int* __restrict__ ib, __half* __restrict__ hh)
{
    int w = (int)((blockIdx.x * blockDim.x + threadIdx.x) >> 5);
    int lane = threadIdx.x & 31;
    if (w < NG)
        agg_row(ib + OI_RP_G1, ib + OI_COL_G1, hh + OH_HU1, hh + OH_BUG, w, lane);
    else if (w < 2*NG)
        agg_row(ib + OI_RP_G2, ib + OI_COL_G2, hh + OH_HI1, hh + OH_BIG, w - NG, lane);
}

// ======================= common GEMM constants ===============================
#define PK   136
#define ROWB (PK * 2)          // 272 B per row
#define TILEB (128 * ROWB)     // 34816 B
#define HTILE (64 * ROWB)      // 17408 B

// ======================= layer-2 GEMM (3 fp16 terms, occ 2) ==================
struct GemmArgs {
    const __half* A[3];
    const __half* W[3];
    const float* bias;
    __half* Ch;
    int M, nterms;
};

#define SMEM_GH (2 * TILEB)    // 69632

__global__ void __launch_bounds__(256, 2)
k_gemm_h(GemmArgs g)
{
    extern __shared__ char sm[];
    const int tid  = threadIdx.x;
    const int wid  = tid >> 5;
    const int lane = tid & 31;
    const int wm   = wid >> 1;
    const int wn   = wid & 1;
    const int m0   = blockIdx.x * 128;

    const uint32_t sbase  = smem_u32(sm);
    const uint32_t a_loff = (uint32_t)(lane & 15) * ROWB + (uint32_t)(lane >> 4) * 16;
    const uint32_t b_loff = (uint32_t)(((lane >> 4) * 8) + (lane & 7)) * ROWB
                          + (uint32_t)((lane >> 3) & 1) * 16;

    float c[2][8][4];
#pragma unroll
    for (int i = 0; i < 2; i++)
#pragma unroll
        for (int j = 0; j < 8; j++)
#pragma unroll
            for (int q = 0; q < 4; q++) c[i][j][q] = 0.f;

#pragma unroll 1
    for (int t = 0; t < g.nterms; t++) {
        const uint4* wsrc = (const uint4*)g.W[t];
        const uint4* asrc = (const uint4*)g.A[t];
#pragma unroll 4
        for (int i = tid; i < 2048; i += 256) {
            int row = i >> 4, cq = i & 15;
            uint32_t so = (uint32_t)row * ROWB + cq * 16;
            *(uint4*)(sm + so) = __ldg(&wsrc[row * 16 + cq]);
            uint4 va = make_uint4(0, 0, 0, 0);
            if (m0 + row < g.M) va = __ldg(&asrc[(size_t)(m0 + row) * 16 + cq]);
            *(uint4*)(sm + TILEB + so) = va;
        }
        __syncthreads();
        uint32_t aB = sbase + TILEB + (uint32_t)wm * 32 * ROWB + a_loff;
        uint32_t bB = sbase + (uint32_t)wn * 64 * ROWB + b_loff;
#pragma unroll
        for (int ks = 0; ks < 8; ks++) {
            uint32_t a[2][4], b[4][4];
            LDSM4(a[0], aB + ks * 32);
            LDSM4(a[1], aB + ks * 32 + 16 * ROWB);
#pragma unroll
            for (int q = 0; q < 4; q++)
                LDSM4(b[q], bB + ks * 32 + q * 16 * ROWB);
#pragma unroll
            for (int ma = 0; ma < 2; ma++)
#pragma unroll
                for (int na = 0; na < 8; na++)
                    MMA_F16(c[ma][na], a[ma],
                            b[na >> 1][(na & 1) * 2], b[na >> 1][(na & 1) * 2 + 1]);
        }
        __syncthreads();
    }

    const int gid = lane >> 2;
    const int tq  = (lane & 3) * 2;
#pragma unroll
    for (int ma = 0; ma < 2; ma++) {
#pragma unroll
        for (int na = 0; na < 8; na++) {
            int mrow = m0 + wm * 32 + ma * 16 + gid;
            int ncol = wn * 64 + na * 8 + tq;
            float2 bv = *(const float2*)(g.bias + ncol);
#pragma unroll
            for (int hrow = 0; hrow < 2; hrow++) {
                int mr = mrow + hrow * 8;
                if (mr >= g.M) continue;
                float v0 = fmaxf(c[ma][na][hrow*2 + 0] + bv.x, 0.f);
                float v1 = fmaxf(c[ma][na][hrow*2 + 1] + bv.y, 0.f);
                __half2 hv = __floats2half2_rn(v0, v1);
                *(__half2*)(g.Ch + (size_t)mr * H + ncol) = hv;
            }
        }
    }
}

// ======================= persistent layer-1 GEMM (fp16, occ 2, 64-row items) =
struct LJob {
    const __half* Ah0; const __half* Ah1;
    const __half* W0;  const __half* W1;
    const float* bias;
    __half* Ch;
    int M, ntiles, ctaBase, nctas;
};
struct LJob3 { LJob j[3]; };

#define SMEM_GL (2 * TILEB + 2 * HTILE)   // 104448
#define NCTA_L 296

__device__ __forceinline__ void loadA64(uint32_t dst, const uint4* ap,
                                        int m0_, int M, int tid)
{
#pragma unroll 2
    for (int i = tid; i < 1024; i += 256) {
        int row = i >> 4, cq = i & 15;
        int gr = m0_ + row;
        int sz = (gr < M) ? 16 : 0;
        if (gr >= M) gr = M - 1;
        CPA16(dst + (uint32_t)row * ROWB + cq * 16, ap + (size_t)gr * 16 + cq, sz);
    }
}

__global__ void __launch_bounds__(256, 2)
k_gemm_l(LJob3 js)
{
    extern __shared__ char sm[];
    const int tid  = threadIdx.x;
    const int wid  = tid >> 5;
    const int lane = tid & 31;
    const int wm   = wid >> 2;
    const int wn   = wid & 3;

    int ji = (blockIdx.x >= (uint32_t)js.j[2].ctaBase) ? 2
           : (blockIdx.x >= (uint32_t)js.j[1].ctaBase) ? 1 : 0;
    const LJob g = js.j[ji];
    const int idx = blockIdx.x - g.ctaBase;
    const int beg = (int)((long long)idx * g.ntiles / g.nctas);
    const int end = (int)((long long)(idx + 1) * g.ntiles / g.nctas);
    if (beg >= end) return;

    const uint32_t sbase = smem_u32(sm);
    const uint32_t sA    = sbase + 2 * TILEB;

    {
        const uint4* w0 = (const uint4*)g.W0;
        const uint4* w1 = (const uint4*)g.W1;
#pragma unroll 4
        for (int i = tid; i < 4096; i += 256) {
            int tl = i >> 11;
            int row = (i >> 4) & 127;
            int cq = i & 15;
            const uint4* src = tl ? w1 : w0;
            CPA16(sbase + (uint32_t)tl * TILEB + (uint32_t)row * ROWB + cq * 16,
                  src + (size_t)row * 16 + cq, 16);
        }
    }
    loadA64(sA, (const uint4*)g.Ah0, beg * 64, g.M, tid);
    CP_COMMIT();

    const uint32_t a_loff = (uint32_t)(lane & 15) * ROWB + (uint32_t)(lane >> 4) * 16;
    const uint32_t b_loff = (uint32_t)(((lane >> 4) * 8) + (lane & 7)) * ROWB
                          + (uint32_t)((lane >> 3) & 1) * 16;
    const int gid = lane >> 2;
    const int tq  = (lane & 3) * 2;

    float c[2][4][4];
    const int nit = (end - beg) * 2;
    int buf = 0;

#pragma unroll 1
    for (int it = 0; it < nit; it++) {
        const int tile = beg + (it >> 1);
        const int term = it & 1;
        if (it + 1 < nit) {
            int ntile = beg + ((it + 1) >> 1);
            int nterm = (it + 1) & 1;
            const uint4* ap = (const uint4*)(nterm ? g.Ah1 : g.Ah0);
            loadA64(sA + (uint32_t)(buf ^ 1) * HTILE, ap, ntile * 64, g.M, tid);
            CP_COMMIT();
            CP_WAIT1();
        } else {
            CP_WAIT0();
        }
        __syncthreads();

        if (term == 0) {
#pragma unroll
            for (int i = 0; i < 2; i++)
#pragma unroll
                for (int j = 0; j < 4; j++)
#pragma unroll
                    for (int q = 0; q < 4; q++) c[i][j][q] = 0.f;
        }

        uint32_t aB = sA + (uint32_t)buf * HTILE + (uint32_t)wm * 32 * ROWB + a_loff;
        uint32_t bB = sbase + (uint32_t)term * TILEB + (uint32_t)wn * 32 * ROWB + b_loff;
#pragma unroll
        for (int ks = 0; ks < 8; ks++) {
            uint32_t a[2][4], b[2][4];
            LDSM4(a[0], aB + ks * 32);
            LDSM4(a[1], aB + ks * 32 + 16 * ROWB);
            LDSM4(b[0], bB + ks * 32);
            LDSM4(b[1], bB + ks * 32 + 16 * ROWB);
#pragma unroll
            for (int ma = 0; ma < 2; ma++)
#pragma unroll
                for (int na = 0; na < 4; na++)
                    MMA_F16(c[ma][na], a[ma],
                            b[na >> 1][(na & 1) * 2], b[na >> 1][(na & 1) * 2 + 1]);
        }

        if (term == 1) {
            int m0_ = tile * 64;
#pragma unroll
            for (int ma = 0; ma < 2; ma++) {
#pragma unroll
                for (int na = 0; na < 4; na++) {
                    int mrow = m0_ + wm * 32 + ma * 16 + gid;
                    int ncol = wn * 32 + na * 8 + tq;
                    float2 bv = *(const float2*)(g.bias + ncol);
#pragma unroll
                    for (int hrow = 0; hrow < 2; hrow++) {
                        int mr = mrow + hrow * 8;
                        if (mr >= g.M) continue;
                        float v0 = fmaxf(c[ma][na][hrow*2 + 0] + bv.x, 0.f);
                        float v1 = fmaxf(c[ma][na][hrow*2 + 1] + bv.y, 0.f);
                        __half2 hv = __floats2half2_rn(v0, v1);
                        *(__half2*)(g.Ch + (size_t)mr * H + ncol) = hv;
                    }
                }
            }
        }
        __syncthreads();
        buf ^= 1;
    }
}

// ======================= persistent pred GEMM (fp32 acc, occupancy 2) ========
#define NTN ((NI + 127) / 128)    // 157
#define NTM ((NG + 127) / 128)    // 40
#define NT_TOT (NTN * NTM)        // 6280
#define NCTA_PRED 296             // 2 CTAs per SM
#define SMEM_PREDH (3 * TILEB)    // 104448

__device__ __forceinline__ void pred_load1(uint32_t dst, const uint4* gp,
                                           int r0_, int rmax, int tid)
{
#pragma unroll 4
    for (int i = tid; i < 2048; i += 256) {
        int row = i >> 4, cq = i & 15;
        int gr = r0_ + row;
        int sz = (gr < rmax) ? 16 : 0;
        if (gr >= rmax) gr = rmax - 1;
        CPA16(dst + (uint32_t)row * ROWB + cq * 16, gp + (size_t)gr * 16 + cq, sz);
    }
}

__global__ void __launch_bounds__(256, 2)
k_mma_pred(const __half* __restrict__ A, const __half* __restrict__ B,
           const float* __restrict__ bias, float* __restrict__ out)
{
    extern __shared__ char sm[];
    const int tid  = threadIdx.x;
    const int wid  = tid >> 5;
    const int lane = tid & 31;
    const int wm   = wid >> 1;
    const int wn   = wid & 1;

    const uint32_t sbase = smem_u32(sm);
    const uint32_t sB    = sbase + TILEB;

    const uint4* gA = (const uint4*)A;
    const uint4* gB = (const uint4*)B;

    const int beg = (int)((long long)blockIdx.x * NT_TOT / NCTA_PRED);
    const int end = (int)((long long)(blockIdx.x + 1) * NT_TOT / NCTA_PRED);

    const uint32_t a_loff = (uint32_t)(lane & 15) * ROWB + (uint32_t)(lane >> 4) * 16;
    const uint32_t b_loff = (uint32_t)(((lane >> 4) * 8) + (lane & 7)) * ROWB
                          + (uint32_t)((lane >> 3) & 1) * 16;
    const int gid = lane >> 2;
    const int tq  = (lane & 3) * 2;

    int cur_m = -1;
    int buf = 0;

#pragma unroll 1
    for (int t = beg; t < end; ++t) {
        int tm = t / NTN, tn = t - tm * NTN;
        if (tm != cur_m) {
            CP_WAIT0();
            __syncthreads();
            pred_load1(sbase, gA, tm * 128, NG, tid);
            pred_load1(sB, gB, tn * 128, NI, tid);
            CP_COMMIT();
            cur_m = tm;
            buf = 0;
            if (t + 1 < end && (t + 1) / NTN == cur_m) {
                pred_load1(sB + TILEB, gB, (tn + 1) * 128, NI, tid);
                CP_COMMIT();
                CP_WAIT1();
            } else {
                CP_WAIT0();
            }
            __syncthreads();
        } else {
            if (t + 1 < end && (t + 1) / NTN == cur_m) {
                pred_load1(sB + (uint32_t)(buf ^ 1) * TILEB, gB, (tn + 1) * 128, NI, tid);
                CP_COMMIT();
                CP_WAIT1();
            } else {
                CP_WAIT0();
            }
            __syncthreads();
        }

        float c[2][8][4];
#pragma unroll
        for (int i = 0; i < 2; i++)
#pragma unroll
            for (int j = 0; j < 8; j++)
#pragma unroll
                for (int q = 0; q < 4; q++) c[i][j][q] = 0.f;

        uint32_t aB = sbase + (uint32_t)wm * 32 * ROWB + a_loff;
        uint32_t bB = sB + (uint32_t)buf * TILEB + (uint32_t)wn * 64 * ROWB + b_loff;
#pragma unroll
        for (int ks = 0; ks < 8; ks++) {
            uint32_t a[2][4], b[4][4];
            LDSM4(a[0], aB + ks * 32);
            LDSM4(a[1], aB + ks * 32 + 16 * ROWB);
#pragma unroll
            for (int q = 0; q < 4; q++)
                LDSM4(b[q], bB + ks * 32 + q * 16 * ROWB);
#pragma unroll
            for (int ma = 0; ma < 2; ma++)
#pragma unroll
                for (int na = 0; na < 8; na++)
                    MMA_F16(c[ma][na], a[ma],
                            b[na >> 1][(na & 1) * 2], b[na >> 1][(na & 1) * 2 + 1]);
        }

        int m0_ = tm * 128, n0_ = tn * 128;
#pragma unroll
        for (int ma = 0; ma < 2; ma++) {
#pragma unroll
            for (int na = 0; na < 8; na++) {
                int mrow = m0_ + wm * 32 + ma * 16 + gid;
                int ncol = n0_ + wn * 64 + na * 8 + tq;
                if (ncol >= NI) continue;
                float2 bv = *(const float2*)(bias + ncol);
                if (mrow < NG) {
                    float2 v = make_float2(c[ma][na][0] + bv.x, c[ma][na][1] + bv.y);
                    *(float2*)(out + (size_t)mrow * NI + ncol) = v;
                }
                if (mrow + 8 < NG) {
                    float2 v = make_float2(c[ma][na][2] + bv.x, c[ma][na][3] + bv.y);
                    *(float2*)(out + (size_t)(mrow + 8) * NI + ncol) = v;
                }
            }
        }
        __syncthreads();
        buf ^= 1;
    }
}

// ---------------------------------------------------------------------------
extern "C" void kernel_launch(void* const* d_in, const int* in_sizes, int n_in,
                              void* d_out, int out_size)
{
    const int*   x_user   = (const int*)  d_in[1];
    const int*   x_item   = (const int*)  d_in[2];
    const float* emb_user = (const float*)d_in[4];
    const float* emb_item = (const float*)d_in[5];
    const float* W1l      = (const float*)d_in[6];
    const float* W1r      = (const float*)d_in[7];
    const float* b1       = (const float*)d_in[8];
    const float* W2l      = (const float*)d_in[9];
    const float* W2r      = (const float*)d_in[10];
    const float* b2       = (const float*)d_in[11];
    const float* pred_W   = (const float*)d_in[12];
    const float* pred_b   = (const float*)d_in[13];
    const int*   ug_src   = (const int*)  d_in[14];
    const int*   ug_dst   = (const int*)  d_in[15];
    const int*   ui_src   = (const int*)  d_in[16];
    const int*   ui_dst   = (const int*)  d_in[17];
    const int*   gi_src   = (const int*)  d_in[18];
    const int*   gi_dst   = (const int*)  d_in[19];
    float* out = (float*)d_out;

    float* fb = nullptr; int* ib = nullptr; __half* hh = nullptr;
    cudaGetSymbolAddress((void**)&fb, g_f);
    cudaGetSymbolAddress((void**)&ib, g_i);
    cudaGetSymbolAddress((void**)&hh, g_h);

    cudaFuncSetAttribute(k_gemm_h, cudaFuncAttributeMaxDynamicSharedMemorySize, SMEM_GH);
    cudaFuncSetAttribute(k_gemm_l, cudaFuncAttributeMaxDynamicSharedMemorySize, SMEM_GL);
    cudaFuncSetAttribute(k_mma_pred, cudaFuncAttributeMaxDynamicSharedMemorySize, SMEM_PREDH);

    // (1) zero degree counts
    cudaMemsetAsync(ib + OI_CNT_G1, 0, (size_t)CNT_TOTAL * sizeof(int));

    // (2) fused front: gather fp16 + degree counts + weight prep (parallel)
    k_front<<<NB_FRONT, 256>>>(emb_user, x_user, emb_item, x_item,
                               ug_dst, gi_src, ui_src, ui_dst,
                               W1l, W1r, W2l, W2r, b1, b2, pred_W,
                               hh, ib);

    // (3) CSR row pointers, (4) bucket
    k_scan4<<<4, 1024>>>(ib);
    {
        int tot = E_UG + E_GI + 2 * E_UI;
        k_bucket_all<<<(tot + 255) / 256, 256>>>(ug_src, ug_dst, ui_src, ui_dst,
                                                 gi_src, gi_dst, ib);
    }

    // (5) layer-1 aggregations  <-- ncu capture slot
    {
        int warps = NU + NI + 2 * NG;
        k_agg_all<<<(warps + 7) / 8, 256>>>(ib, hh);
    }

    // (6) layer-1 GEMMs: persistent, occupancy 2 (64-row items)
    {
        LJob3 js;
        js.j[0].Ah0 = hh + OH_AIU; js.j[0].Ah1 = hh + OH_HU;
        js.j[0].W0 = hh + OH_W + SL_W1L3*HH; js.j[0].W1 = hh + OH_W + SL_WC0*HH;
        js.j[0].bias = fb + 0*H; js.j[0].Ch = hh + OH_HU1;
        js.j[0].M = NU; js.j[0].ntiles = (NU + 63) / 64;
        js.j[0].ctaBase = 0;   js.j[0].nctas = 236;
        js.j[1].Ah0 = hh + OH_AUI; js.j[1].Ah1 = hh + OH_HI;
        js.j[1].W0 = hh + OH_W + SL_W1L2*HH; js.j[1].W1 = hh + OH_W + SL_WC1*HH;
        js.j[1].bias = fb + 1*H; js.j[1].Ch = hh + OH_HI1;
        js.j[1].M = NI; js.j[1].ntiles = (NI + 63) / 64;
        js.j[1].ctaBase = 236; js.j[1].nctas = 48;
        js.j[2].Ah0 = hh + OH_AUG; js.j[2].Ah1 = hh + OH_AIG;
        js.j[2].W0 = hh + OH_W + SL_W1L0*HH; js.j[2].W1 = hh + OH_W + SL_W1L5*HH;
        js.j[2].bias = fb + 2*H; js.j[2].Ch = hh + OH_HG1;
        js.j[2].M = NG; js.j[2].ntiles = (NG + 63) / 64;
        js.j[2].ctaBase = 284; js.j[2].nctas = 12;
        k_gemm_l<<<NCTA_L, 256, SMEM_GL>>>(js);
    }

    // (7) layer-2 aggregations
    k_agg_all2<<<(2 * NG + 7) / 8, 256>>>(ib, hh);

    // (8) layer-2 group GEMM (3 fp16 terms) -> REP fp16
    {
        GemmArgs a;
        a.A[0] = hh + OH_BUG; a.W[0] = hh + OH_W + SL_W2L0*HH;
        a.A[1] = hh + OH_HG1; a.W[1] = hh + OH_W + SL_WC2*HH;
        a.A[2] = hh + OH_BIG; a.W[2] = hh + OH_W + SL_W2L5*HH;
        a.bias = fb + 3*H;
        a.Ch = hh + OH_REP;
        a.M = NG; a.nterms = 3;
        k_gemm_h<<<(NG + 127) / 128, 256, SMEM_GH>>>(a);
    }

    // (9) persistent fp32-acc prediction GEMM at occupancy 2
    k_mma_pred<<<NCTA_PRED, 256, SMEM_PREDH>>>(hh + OH_REP, hh + OH_PW, pred_b, out);
    (void)in_sizes; (void)n_in; (void)out_size;
}